// round 17
// baseline (speedup 1.0000x reference)
#include <cuda_runtime.h>

// BezierToImageLayer — sparse Gaussian splat, round 17.
// R17 = R16 body (SHFL-free Horner with literal t_s, phased pair-RMW, issue 71.5%)
// + NSPLIT=5 (grid 1280):
//  - wave-quantization model: 444 concurrent CTA slots (148 SM x 3 CTAs).
//    grid 1024 -> makespan 3 CTA-durations for 2.31 durations of work (77% util).
//    grid 1280 -> makespan 3 x (32-curve CTA) = 0.8x the NSPLIT=4 makespan (96% util).
//  - CPT=32, PAIRS_W=4 (exact divisibility). Combine reads 5 partials.

#define BDIM     128
#define NWARPS   4
#define NSPLIT   5
#define WPIX     60
#define AROWS    67                         // rows -3..63
#define STRIDE   68                         // bank-pair (2i+P) mod 16: 2-phase LDS.64
#define RPAD     3
#define CPAD     4
#define NSAMP    30
#define NCURVE   160
#define CPT      (NCURVE / NSPLIT)          // 32 curves per task
#define PAIRS_W  (CPT / NWARPS / 2)         // 4 curve-pairs per warp
#define COPY_W   (AROWS * STRIDE)           // 4556 floats
#define ACC_WORDS (NWARPS * COPY_W)         // 18224 floats = 72896 B

#define NBATCH   256
#define IMG      (WPIX * WPIX)

__device__ float g_scratch[NBATCH * NSPLIT * IMG];   // 18.4 MB partials (L2-hot)
__device__ int   g_cnt[NBATCH];                      // zero-init; reset by last CTA

__device__ __forceinline__ float ex2f(float a) {
    float r; asm("ex2.approx.f32 %0, %1;" : "=f"(r) : "f"(a)); return r;
}

__global__ __launch_bounds__(BDIM, 3)
void bezier_splat_kernel(const float* __restrict__ x, float* __restrict__ out)
{
    extern __shared__ float acc[];   // [NWARPS][AROWS][STRIDE], per-warp private

    const int task = blockIdx.x;          // 0..1279
    const int b    = task / NSPLIT;
    const int part = task - b * NSPLIT;
    const int tid  = threadIdx.x;
    const int w    = tid >> 5;
    const int lane = tid & 31;

    // ---- zero private accumulators ----
    float4* az = (float4*)acc;
    for (int i = tid; i < ACC_WORDS / 4; i += BDIM)
        az[i] = make_float4(0.f, 0.f, 0.f, 0.f);
    __syncthreads();

    float* __restrict__ my = acc + w * COPY_W + RPAD * STRIDE + CPAD;

    const int half = lane >> 4;        // which curve of the pair
    const int hb   = half << 1;        // phase-order swap for half 1
    const int hl   = lane & 15;
    const int q    = hl & 1;           // base col-pair residue (mod 4)
    const int rl3  = (hl >> 1) + 3;    // row residue (mod 8), pre-biased

    const float C2 = -2.0037431123457827f;   // -(5000/3600)*log2(e) = -K*K
    const float K  = 1.4155363231368842f;    // sqrt(-C2)
    const float K4 = 4.0f * K;

    const float* __restrict__ xb = x + ((size_t)b * NCURVE + part * CPT) * 8;

    for (int cp = 0; cp < PAIRS_W; ++cp) {
        const int pi = w + NWARPS * cp;               // pair index 0..15
        const float* ct = xb + (2 * pi + half) * 8;   // uniform per half-warp

        // control points in pixel units; power basis (uniform per half-warp)
        const float p0x = 60.0f * ct[0], p0y = 60.0f * ct[1];
        const float p1x = 60.0f * ct[2], p1y = 60.0f * ct[3];
        const float p2x = 60.0f * ct[4], p2y = 60.0f * ct[5];
        const float p3x = 60.0f * ct[6], p3y = 60.0f * ct[7];
        const float c0x = p3x;
        const float c1x = 3.0f * (p2x - p3x);
        const float c2x = 3.0f * (p1x - 2.0f * p2x + p3x);
        const float c3x = (p0x - p3x) + 3.0f * (p2x - p1x);
        const float c0y = p3y;
        const float c1y = 3.0f * (p2y - p3y);
        const float c2y = 3.0f * (p1y - 2.0f * p2y + p3y);
        const float c3y = (p0y - p3y) + 3.0f * (p2y - p1y);

        #pragma unroll
        for (int s = 0; s < NSAMP; ++s) {
            // t_s folds to a literal after full unroll -> FFMA-imm Horner (no SHFL)
            const float uu = (float)s * (1.0f / 30.0f);
            const float tt = 2.0f*uu*uu*uu - 3.0f*uu*uu + 2.0f*uu;

            const float Xp = fmaf(fmaf(fmaf(c3x, tt, c2x), tt, c1x), tt, c0x);
            const float Yp = fmaf(fmaf(fmaf(c3y, tt, c2y), tt, c1y), tt, c0y);

            int mi = (int)Xp;  mi = min(mi, WPIX - 1);   // guard vs Horner rounding
            int mj = (int)Yp;  mj = min(mj, WPIX - 1);

            const int i    = mi - 3 + ((rl3 - mi) & 7);   // row, ≡ rl (mod 8)
            const int P0   = (mj - 3) >> 1;
            const int off1 = (((q - P0) & 3) ^ hb);       // phase-1 residue set
            const int P1   = P0 + off1;
            const int P2   = P1 + ((off1 & 2) ? -2 : 2);  // off2 = off1 ^ 2

            const float dx  = ((float)i        - Xp) * K;
            const float dy1 = ((float)(2 * P1) - Yp) * K;
            const float dy2 = dy1 + ((off1 & 2) ? -K4 : K4);

            const float nx  = -(dx * dx);
            const float e1  = fmaf(dy1, -dy1, nx);
            const float e2  = fmaf(dy2, -dy2, nx);
            const float td1 = fmaf(dy1, -2.0f * K, C2);
            const float td2 = fmaf(dy2, -2.0f * K, C2);

            const float g11 = ex2f(e1);
            const float g12 = ex2f(e1 + td1);
            const float g21 = ex2f(e2);
            const float g22 = ex2f(e2 + td2);

            float* __restrict__ row = my + i * STRIDE;

            // phase 1: halves on disjoint pair-residues -> race-free within instr
            {
                float2* p1 = (float2*)(row + 2 * P1);
                float2 v = *p1;
                v.x += g11; v.y += g12;
                *p1 = v;
            }
            // ordering fence: phase-2 LDS must not hoist above phase-1 STS
            asm volatile("" ::: "memory");
            // phase 2: swapped residue sets; cross-phase ordered by program order
            {
                float2* p2 = (float2*)(row + 2 * P2);
                float2 v = *p2;
                v.x += g21; v.y += g22;
                *p2 = v;
            }
        }
    }
    __syncthreads();

    // ---- reduce 4 private copies -> scratch partial (float4) ----
    float4* __restrict__ sp4 = (float4*)(g_scratch + (size_t)task * IMG);
    const float* __restrict__ a0 = acc + RPAD * STRIDE + CPAD;
    for (int qd = tid; qd < IMG / 4; qd += BDIM) {        // 900 quads
        const int i = qd / (WPIX / 4);
        const int k = qd - i * (WPIX / 4);
        const int o = i * STRIDE + 4 * k;
        float4 s0 = *(const float4*)(a0 + o);
        #pragma unroll
        for (int ww = 1; ww < NWARPS; ++ww) {
            const float4 v = *(const float4*)(a0 + ww * COPY_W + o);
            s0.x += v.x; s0.y += v.y; s0.z += v.z; s0.w += v.w;
        }
        sp4[qd] = s0;
    }

    // ---- last task of this batch combines the 5 partials ----
    __threadfence();
    __syncthreads();
    __shared__ int s_last;
    if (tid == 0) {
        int old = atomicAdd(&g_cnt[b], 1);
        s_last = (old == NSPLIT - 1);
    }
    __syncthreads();
    if (s_last) {
        __threadfence();   // acquire: see all tasks' scratch writes
        const float4* __restrict__ base4 =
            (const float4*)(g_scratch + (size_t)b * NSPLIT * IMG);
        float4* __restrict__ ob = (float4*)(out + (size_t)b * IMG);
        for (int qd = tid; qd < IMG / 4; qd += BDIM) {
            float4 s0 = base4[qd];
            #pragma unroll
            for (int k = 1; k < NSPLIT; ++k) {
                const float4 v = base4[k * (IMG / 4) + qd];
                s0.x += v.x; s0.y += v.y; s0.z += v.z; s0.w += v.w;
            }
            s0.x = fminf(s0.x, 1.0f);
            s0.y = fminf(s0.y, 1.0f);
            s0.z = fminf(s0.z, 1.0f);
            s0.w = fminf(s0.w, 1.0f);
            ob[qd] = s0;
        }
        if (tid == 0) g_cnt[b] = 0;   // reset for next graph replay
    }
}

extern "C" void kernel_launch(void* const* d_in, const int* in_sizes, int n_in,
                              void* d_out, int out_size)
{
    (void)in_sizes; (void)n_in; (void)out_size;
    const float* x = (const float*)d_in[0];
    float* out     = (float*)d_out;

    cudaFuncSetAttribute(bezier_splat_kernel,
                         cudaFuncAttributeMaxDynamicSharedMemorySize,
                         ACC_WORDS * (int)sizeof(float));

    bezier_splat_kernel<<<NBATCH * NSPLIT, BDIM, ACC_WORDS * (int)sizeof(float)>>>(x, out);
}